// round 1
// baseline (speedup 1.0000x reference)
#include <cuda_runtime.h>

// ---------------------------------------------------------------------------
// Constants
// ---------------------------------------------------------------------------
#define GAIN   1.6778523489932886f   // 1/0.596
#define MPA_A  0.9191450300180579f   // 0.7 / sqrt(0.58)
#define MPA_B  0.3939192985791677f   // 0.3 / sqrt(0.58)

__device__ __forceinline__ float siluG(float v) {
    // mp_silu: silu(v) * GAIN
    return GAIN * v / (1.0f + __expf(-v));
}

// ---------------------------------------------------------------------------
// Static device scratch (no runtime allocation allowed)
// ---------------------------------------------------------------------------
__device__ float g_xn [33554432];   // pixel-normed activation (needed for mp_add)
__device__ float g_y  [33554432];   // silu(pn) input / zc / h buffer
__device__ float g_r1 [67108864];   // mid activation (2C channels)
__device__ float g_rd [67108864];   // depthwise output / a,b / gated h
__device__ float g_act[33554432];   // current block input/output
__device__ float g_wn [ 4194304];   // normalized weights scratch

// offsets inside g_wn
#define WA 0          // up to 2,097,152 (gru_w / w1)
#define WB 2097152    // up to 1,048,576 (hg_w / w2)
#define WC 3145728    // up to   524,288 (out_w / dn)
#define WD 3670016    // small (wd / dw_w)

#define AB_OFF 4194304L     // offset of b inside g_rd (a at 0)
#define HS_OFF 16777216L    // offset of scan output inside g_y

// ---------------------------------------------------------------------------
// Weight normalization: one block per output filter row
// ---------------------------------------------------------------------------
__global__ void normw_kernel(const float* __restrict__ w, float* __restrict__ o, int rlen) {
    int r = blockIdx.x;
    const float* wr = w + (size_t)r * rlen;
    float* orow = o + (size_t)r * rlen;
    float s = 0.f;
    for (int i = threadIdx.x; i < rlen; i += blockDim.x) { float v = wr[i]; s += v * v; }
    __shared__ float sd[256];
    sd[threadIdx.x] = s;
    __syncthreads();
    for (int st = 128; st > 0; st >>= 1) {
        if (threadIdx.x < st) sd[threadIdx.x] += sd[threadIdx.x + st];
        __syncthreads();
    }
    float inv = rsqrtf(sd[0] + 1e-8f);
    for (int i = threadIdx.x; i < rlen; i += blockDim.x) orow[i] = wr[i] * inv;
}

// ---------------------------------------------------------------------------
// Projection: out[b,c,f,l] = audio[b,f,l]*pw[c] + pb[c]
// ---------------------------------------------------------------------------
__global__ void proj_kernel(const float* __restrict__ audio, const float* __restrict__ pw,
                            const float* __restrict__ pb, float* __restrict__ out,
                            int S, long total) {
    long idx = (long)blockIdx.x * blockDim.x + threadIdx.x;
    if (idx >= total) return;
    long p = idx % S;
    int  c = (int)((idx / S) % 64);
    long b = idx / ((long)64 * S);
    out[idx] = audio[b * S + p] * pw[c] + pb[c];
}

// ---------------------------------------------------------------------------
// Pixel norm over channels; optionally also write silu(pn)*GAIN
// ---------------------------------------------------------------------------
__global__ void pn_kernel(const float* __restrict__ x, float* __restrict__ xn,
                          float* __restrict__ y, int C, int S, long total) {
    long idx = (long)blockIdx.x * blockDim.x + threadIdx.x;
    if (idx >= total) return;                       // total = B*S
    long b = idx / S;
    long p = idx % S;
    const float* xp = x + (b * C) * (long)S + p;
    float sum = 0.f;
    for (int c = 0; c < C; c++) { float v = xp[(long)c * S]; sum += v * v; }
    float inv = rsqrtf(sum / C + 1e-4f);
    float* xnp = xn + (b * C) * (long)S + p;
    if (y) {
        float* yp = y + (b * C) * (long)S + p;
        for (int c = 0; c < C; c++) {
            float v = xp[(long)c * S] * inv;
            xnp[(long)c * S] = v;
            yp [(long)c * S] = siluG(v);
        }
    } else {
        for (int c = 0; c < C; c++) xnp[(long)c * S] = xp[(long)c * S] * inv;
    }
}

// ---------------------------------------------------------------------------
// Tiled SGEMM: Y[b] = W(MxK) @ X[b](KxN).  EPI=1: Y = mp_add(XN, W@X)
// Requires M%64==0, N%64==0, K%16==0 (holds for all shapes here).
// ---------------------------------------------------------------------------
template <int EPI>
__global__ void __launch_bounds__(256) sgemm_kernel(
    const float* __restrict__ W, const float* __restrict__ X,
    float* __restrict__ Y, const float* __restrict__ XN,
    int M, int K, int N) {
    __shared__ float Ws[16][65];
    __shared__ float Xs[16][65];
    int tid = threadIdx.x;
    int tx = tid & 15, ty = tid >> 4;
    int m0 = blockIdx.y * 64, n0 = blockIdx.x * 64;
    long bofX = (long)blockIdx.z * K * N;
    long bofY = (long)blockIdx.z * M * N;
    float acc[4][4] = {};
    for (int k0 = 0; k0 < K; k0 += 16) {
#pragma unroll
        for (int i = 0; i < 4; i++) {
            int flat = tid + i * 256;
            int m = flat >> 4, k = flat & 15;
            Ws[k][m] = W[(long)(m0 + m) * K + k0 + k];
        }
#pragma unroll
        for (int i = 0; i < 4; i++) {
            int flat = tid + i * 256;
            int k = flat >> 6, n = flat & 63;
            Xs[k][n] = X[bofX + (long)(k0 + k) * N + n0 + n];
        }
        __syncthreads();
#pragma unroll
        for (int k = 0; k < 16; k++) {
            float wv[4], xv[4];
#pragma unroll
            for (int i = 0; i < 4; i++) wv[i] = Ws[k][ty * 4 + i];
#pragma unroll
            for (int j = 0; j < 4; j++) xv[j] = Xs[k][tx * 4 + j];
#pragma unroll
            for (int i = 0; i < 4; i++)
#pragma unroll
                for (int j = 0; j < 4; j++)
                    acc[i][j] = fmaf(wv[i], xv[j], acc[i][j]);
        }
        __syncthreads();
    }
#pragma unroll
    for (int i = 0; i < 4; i++) {
        int m = m0 + ty * 4 + i;
#pragma unroll
        for (int j = 0; j < 4; j++) {
            int n = n0 + tx * 4 + j;
            float v = acc[i][j];
            if (EPI == 1) v = fmaf(MPA_A, XN[bofY + (long)m * N + n], MPA_B * v);
            Y[bofY + (long)m * N + n] = v;
        }
    }
}

// ---------------------------------------------------------------------------
// Depthwise 5x3 conv2d (pad F:2, L:1), fused mp_silu on output
// ---------------------------------------------------------------------------
__global__ void dwconv2d_kernel(const float* __restrict__ in, const float* __restrict__ wd,
                                float* __restrict__ out, int C, int F, int L) {
    int l  = blockIdx.x * blockDim.x + threadIdx.x;
    int f  = blockIdx.y;
    int zc = blockIdx.z;          // b*C + c
    int c  = zc % C;
    const float* ip = in + (long)zc * F * L;
    const float* w  = wd + c * 15;
    float acc = 0.f;
#pragma unroll
    for (int kf = 0; kf < 5; kf++) {
        int ff = f + kf - 2;
        if (ff < 0 || ff >= F) continue;
        const float* row = ip + (long)ff * L;
#pragma unroll
        for (int kl = 0; kl < 3; kl++) {
            int ll = l + kl - 1;
            if (ll < 0 || ll >= L) continue;
            acc = fmaf(w[kf * 3 + kl], row[ll], acc);
        }
    }
    out[(long)zc * F * L + (long)f * L + l] = siluG(acc);
}

// ---------------------------------------------------------------------------
// Avg-pool over freq groups of s
// ---------------------------------------------------------------------------
__global__ void pool_kernel(const float* __restrict__ in, float* __restrict__ out,
                            int F, int L, int s, long total) {
    long idx = (long)blockIdx.x * blockDim.x + threadIdx.x;
    if (idx >= total) return;                       // total = B*C*Fo*L
    int Fo = F / s;
    long l  = idx % L;
    long fo = (idx / L) % Fo;
    long bc = idx / ((long)L * Fo);
    const float* ip = in + bc * (long)F * L + fo * s * (long)L + l;
    float acc = 0.f;
    for (int j = 0; j < s; j++) acc += ip[(long)j * L];
    out[idx] = acc * (1.0f / s);
}

// ---------------------------------------------------------------------------
// Depthwise 1D conv k=3 pad 1; input is h-half (ch 0..1023) of 2048-ch buffer;
// mp_silu applied to input AND output (matches silu -> dwconv -> silu chain)
// ---------------------------------------------------------------------------
__global__ void dwconv1d_kernel(const float* __restrict__ in, const float* __restrict__ w,
                                float* __restrict__ out, int T, long total) {
    long idx = (long)blockIdx.x * blockDim.x + threadIdx.x;
    if (idx >= total) return;                       // total = B*1024*T
    int  t = (int)(idx % T);
    int  c = (int)((idx / T) % 1024);
    long b = idx / ((long)1024 * T);
    const float* ip = in + ((b * 2048) + c) * (long)T;
    const float* wc = w + c * 3;
    float acc = 0.f;
    if (t > 0)     acc = fmaf(wc[0], siluG(ip[t - 1]), acc);
    acc = fmaf(wc[1], siluG(ip[t]), acc);
    if (t < T - 1) acc = fmaf(wc[2], siluG(ip[t + 1]), acc);
    out[idx] = siluG(acc);
}

// ---------------------------------------------------------------------------
// minGRU pre-scan: a = 1-sigmoid(z), b = sigmoid(z)*c
// ---------------------------------------------------------------------------
__global__ void ab_kernel(const float* __restrict__ zc, float* __restrict__ a,
                          float* __restrict__ b_, int T, long total) {
    long idx = (long)blockIdx.x * blockDim.x + threadIdx.x;
    if (idx >= total) return;                       // total = B*1024*T
    int  t = (int)(idx % T);
    int  c = (int)((idx / T) % 1024);
    long b = idx / ((long)1024 * T);
    long base = ((b * 2048) + c) * (long)T + t;
    float z  = zc[base];
    float cc = zc[base + (long)1024 * T];
    float s  = 1.f / (1.f + __expf(-z));
    a [idx] = 1.f - s;
    b_[idx] = s * cc;
}

// ---------------------------------------------------------------------------
// Sequential first-order scan per (b, channel) row
// ---------------------------------------------------------------------------
__global__ void scan_kernel(const float* __restrict__ a, const float* __restrict__ b,
                            float* __restrict__ h, int T) {
    int row = blockIdx.x * blockDim.x + threadIdx.x; // 0..2047
    const float* ar = a + (long)row * T;
    const float* br = b + (long)row * T;
    float* hr = h + (long)row * T;
    float s = 0.f;
    for (int t = 0; t < T; t++) { s = fmaf(ar[t], s, br[t]); hr[t] = s; }
}

// ---------------------------------------------------------------------------
// Gate: out = h_scan * mp_silu(g)   (g = ch 1024..2047 of hg buffer)
// ---------------------------------------------------------------------------
__global__ void gate_kernel(const float* __restrict__ hsc, const float* __restrict__ hg,
                            float* __restrict__ out, int T, long total) {
    long idx = (long)blockIdx.x * blockDim.x + threadIdx.x;
    if (idx >= total) return;
    int  t = (int)(idx % T);
    int  c = (int)((idx / T) % 1024);
    long b = idx / ((long)1024 * T);
    float g = hg[((b * 2048) + 1024 + c) * (long)T + t];
    out[idx] = hsc[idx] * siluG(g);
}

// ---------------------------------------------------------------------------
// Final mp_silu
// ---------------------------------------------------------------------------
__global__ void msilu_kernel(const float* __restrict__ in, float* __restrict__ out, long n) {
    long idx = (long)blockIdx.x * blockDim.x + threadIdx.x;
    if (idx < n) out[idx] = siluG(in[idx]);
}

// ---------------------------------------------------------------------------
// Host orchestration
// ---------------------------------------------------------------------------
static inline dim3 gs(long total, int bs) { return dim3((unsigned)((total + bs - 1) / bs)); }

extern "C" void kernel_launch(void* const* d_in, const int* in_sizes, int n_in,
                              void* d_out, int out_size) {
    const float* audio = (const float*)d_in[0];
    const float* projw = (const float*)d_in[1];
    const float* projb = (const float*)d_in[2];
    const float* bw[3][4];
    for (int i = 0; i < 3; i++)
        for (int j = 0; j < 4; j++)
            bw[i][j] = (const float*)d_in[3 + i * 4 + j];  // w1, wd, w2, dn
    const float* hgw_all  = (const float*)d_in[15];
    const float* dww_all  = (const float*)d_in[16];
    const float* gruw_all = (const float*)d_in[17];
    const float* outw_all = (const float*)d_in[18];

    float *xn, *y, *r1, *rd, *act, *wn;
    cudaGetSymbolAddress((void**)&xn,  g_xn);
    cudaGetSymbolAddress((void**)&y,   g_y);
    cudaGetSymbolAddress((void**)&r1,  g_r1);
    cudaGetSymbolAddress((void**)&rd,  g_rd);
    cudaGetSymbolAddress((void**)&act, g_act);
    cudaGetSymbolAddress((void**)&wn,  g_wn);

    const int B = 2, L = 2048;

    // --- projection ---
    {
        long total = (long)B * 64 * 128 * L;
        proj_kernel<<<gs(total, 256), 256>>>(audio, projw, projb, act, 128 * L, total);
    }

    // --- conv blocks ---
    int C = 64, F = 128;
    const int scales[3] = {4, 4, 8};
    for (int blk = 0; blk < 3; blk++) {
        int C2 = 2 * C;
        int S  = F * L;
        normw_kernel<<<C2, 256>>>(bw[blk][0], wn + WA, C);   // w1  (2C x C)
        normw_kernel<<<C2, 256>>>(bw[blk][1], wn + WD, 15);  // wd  (2C x 15)
        normw_kernel<<<C , 256>>>(bw[blk][2], wn + WB, C2);  // w2  (C x 2C)
        normw_kernel<<<C2, 256>>>(bw[blk][3], wn + WC, C);   // dn  (2C x C)

        long totP = (long)B * S;
        pn_kernel<<<gs(totP, 256), 256>>>(act, xn, y, C, S, totP);

        sgemm_kernel<0><<<dim3(S / 64, C2 / 64, B), 256>>>(wn + WA, y, r1, nullptr, C2, C, S);
        dwconv2d_kernel<<<dim3(L / 128, F, B * C2), 128>>>(r1, wn + WD, rd, C2, F, L);
        sgemm_kernel<1><<<dim3(S / 64, C / 64, B), 256>>>(wn + WB, rd, y, xn, C, C2, S);

        int s = scales[blk], Fo = F / s;
        long totPool = (long)B * C * Fo * L;
        pool_kernel<<<gs(totPool, 256), 256>>>(y, r1, F, L, s, totPool);

        int S2 = Fo * L;
        sgemm_kernel<0><<<dim3(S2 / 64, C2 / 64, B), 256>>>(wn + WC, r1, act, nullptr, C2, C, S2);
        C = C2; F = Fo;
    }

    // --- sequence blocks (C = 512, act: (B, 512, 2048)) ---
    const int T = 2048;
    for (int i = 0; i < 4; i++) {
        const float* hgw  = hgw_all  + (long)i * 2048 * 512;
        const float* dww  = dww_all  + (long)i * 1024 * 3;
        const float* gruw = gruw_all + (long)i * 2048 * 1024;
        const float* outw = outw_all + (long)i * 512 * 1024;
        normw_kernel<<<2048, 256>>>(hgw,  wn + WB, 512);
        normw_kernel<<<1024, 256>>>(dww,  wn + WD, 3);
        normw_kernel<<<2048, 256>>>(gruw, wn + WA, 1024);
        normw_kernel<<< 512, 256>>>(outw, wn + WC, 1024);

        long totP = (long)B * T;
        pn_kernel<<<gs(totP, 256), 256>>>(act, xn, nullptr, 512, T, totP);

        sgemm_kernel<0><<<dim3(T / 64, 2048 / 64, B), 256>>>(wn + WB, xn, r1, nullptr, 2048, 512, T);

        long tot1 = (long)B * 1024 * T;
        dwconv1d_kernel<<<gs(tot1, 256), 256>>>(r1, wn + WD, rd, T, tot1);

        sgemm_kernel<0><<<dim3(T / 64, 2048 / 64, B), 256>>>(wn + WA, rd, y, nullptr, 2048, 1024, T);

        ab_kernel<<<gs(tot1, 256), 256>>>(y, rd, rd + AB_OFF, T, tot1);
        scan_kernel<<<16, 128>>>(rd, rd + AB_OFF, y + HS_OFF, T);
        gate_kernel<<<gs(tot1, 256), 256>>>(y + HS_OFF, r1, rd, T, tot1);

        sgemm_kernel<1><<<dim3(T / 64, 512 / 64, B), 256>>>(wn + WC, rd, act, xn, 512, 1024, T);
    }

    // --- final mp_silu ---
    msilu_kernel<<<gs(out_size, 256), 256>>>(act, (float*)d_out, (long)out_size);
}

// round 2
// speedup vs baseline: 1.3699x; 1.3699x over previous
#include <cuda_runtime.h>

// ---------------------------------------------------------------------------
// Constants
// ---------------------------------------------------------------------------
#define GAIN   1.6778523489932886f   // 1/0.596
#define MPA_A  0.9191450300180579f   // 0.7 / sqrt(0.58)
#define MPA_B  0.3939192985791677f   // 0.3 / sqrt(0.58)

typedef unsigned long long u64;

__device__ __forceinline__ float siluG(float v) {
    return GAIN * v / (1.0f + __expf(-v));
}

// packed f32x2 FMA: c = a*b + c (elementwise on 2 packed floats)
__device__ __forceinline__ void fma2(u64 &c, u64 a, u64 b) {
    asm("fma.rn.f32x2 %0, %1, %2, %0;" : "+l"(c) : "l"(a), "l"(b));
}
__device__ __forceinline__ float f2lo(u64 v) { return __uint_as_float((unsigned)v); }
__device__ __forceinline__ float f2hi(u64 v) { return __uint_as_float((unsigned)(v >> 32)); }

// ---------------------------------------------------------------------------
// Static device scratch
// ---------------------------------------------------------------------------
__device__ float g_xn [33554432];
__device__ float g_y  [33554432];
__device__ float g_r1 [67108864];
__device__ float g_rd [67108864];
__device__ float g_act[33554432];
__device__ float g_wn [ 4194304];

#define WA 0
#define WB 2097152
#define WC 3145728
#define WD 3670016

// ---------------------------------------------------------------------------
// Weight normalization
// ---------------------------------------------------------------------------
__global__ void normw_kernel(const float* __restrict__ w, float* __restrict__ o, int rlen) {
    int r = blockIdx.x;
    const float* wr = w + (size_t)r * rlen;
    float* orow = o + (size_t)r * rlen;
    float s = 0.f;
    for (int i = threadIdx.x; i < rlen; i += blockDim.x) { float v = wr[i]; s += v * v; }
    __shared__ float sd[256];
    sd[threadIdx.x] = s;
    __syncthreads();
    for (int st = 128; st > 0; st >>= 1) {
        if (threadIdx.x < st) sd[threadIdx.x] += sd[threadIdx.x + st];
        __syncthreads();
    }
    float inv = rsqrtf(sd[0] + 1e-8f);
    for (int i = threadIdx.x; i < rlen; i += blockDim.x) orow[i] = wr[i] * inv;
}

// ---------------------------------------------------------------------------
// Projection
// ---------------------------------------------------------------------------
__global__ void proj_kernel(const float* __restrict__ audio, const float* __restrict__ pw,
                            const float* __restrict__ pb, float* __restrict__ out,
                            int S, long total) {
    long idx = (long)blockIdx.x * blockDim.x + threadIdx.x;
    if (idx >= total) return;
    long p = idx % S;
    int  c = (int)((idx / S) % 64);
    long b = idx / ((long)64 * S);
    out[idx] = audio[b * S + p] * pw[c] + pb[c];
}

// ---------------------------------------------------------------------------
// Pixel norm (conv blocks): thread-per-position, writes xn and y=siluG(xn)
// ---------------------------------------------------------------------------
__global__ void pn_kernel(const float* __restrict__ x, float* __restrict__ xn,
                          float* __restrict__ y, int C, int S, long total) {
    long idx = (long)blockIdx.x * blockDim.x + threadIdx.x;
    if (idx >= total) return;
    long b = idx / S;
    long p = idx % S;
    const float* xp = x + (b * C) * (long)S + p;
    float sum = 0.f;
    for (int c = 0; c < C; c++) { float v = xp[(long)c * S]; sum += v * v; }
    float inv = rsqrtf(sum / C + 1e-4f);
    float* xnp = xn + (b * C) * (long)S + p;
    float* yp  = y  + (b * C) * (long)S + p;
    for (int c = 0; c < C; c++) {
        float v = xp[(long)c * S] * inv;
        xnp[(long)c * S] = v;
        yp [(long)c * S] = siluG(v);
    }
}

// ---------------------------------------------------------------------------
// Pixel norm (seq blocks): warp-sliced over channels, lane = position
// block = 256 thr = 8 warps handling 32 positions; C must be divisible by 8
// ---------------------------------------------------------------------------
__global__ void pn_seq_kernel(const float* __restrict__ x, float* __restrict__ xn,
                              int C, int T) {
    int lane = threadIdx.x & 31, w = threadIdx.x >> 5;
    long p0 = (long)blockIdx.x * 32;
    long b = p0 / T;
    long p = (p0 % T) + lane;
    int cpw = C / 8;
    const float* xp = x + (b * C + (long)w * cpw) * (long)T + p;
    float s = 0.f;
    for (int c = 0; c < cpw; c++) { float v = xp[(long)c * T]; s += v * v; }
    __shared__ float ps[8][32];
    __shared__ float inv[32];
    ps[w][lane] = s;
    __syncthreads();
    if (threadIdx.x < 32) {
        float tot = 0.f;
        for (int i = 0; i < 8; i++) tot += ps[i][threadIdx.x];
        inv[threadIdx.x] = rsqrtf(tot / C + 1e-4f);
    }
    __syncthreads();
    float iv = inv[lane];
    float* op = xn + (b * C + (long)w * cpw) * (long)T + p;
    for (int c = 0; c < cpw; c++) op[(long)c * T] = xp[(long)c * T] * iv;
}

// ---------------------------------------------------------------------------
// FFMA2 SGEMM: Y[b] = W(MxK) @ X[b](KxN); EPI=1: Y = mp_add(XN, W@X)
// BM in {64,128}; BN=128; BK=16; 256 threads; per-thread (BM/16) x 8 outputs.
// W duplicated in smem as packed (w,w) u64 pairs.
// ---------------------------------------------------------------------------
template <int EPI, int BM>
__global__ void __launch_bounds__(256, 2) gemm2_kernel(
    const float* __restrict__ W, const float* __restrict__ X,
    float* __restrict__ Y, const float* __restrict__ XN,
    int M, int K, int N) {
    constexpr int MT  = BM / 16;            // rows per thread (8 or 4)
    constexpr int WLD = (BM * 16) / 1024;   // float4 W-loads per thread (2 or 1)
    __shared__ __align__(16) u64   WsD[16][BM];   // duplicated W pairs
    __shared__ __align__(16) float Xs [16][128];

    int tid = threadIdx.x;
    int tx = tid & 15, ty = tid >> 4;
    int m0 = blockIdx.y * BM, n0 = blockIdx.x * 128;
    long bX = (long)blockIdx.z * K * N;
    long bY = (long)blockIdx.z * M * N;

    u64 acc[MT][4];
#pragma unroll
    for (int i = 0; i < MT; i++)
#pragma unroll
        for (int j = 0; j < 4; j++) acc[i][j] = 0ull;

    float4 wreg[2], xreg[2];

    // ---- load helpers ----
    auto loadW = [&](int k0) {
#pragma unroll
        for (int q = 0; q < WLD; q++) {
            int e = tid + q * 256;
            int m = e >> 2, kq = e & 3;
            wreg[q] = *(const float4*)&W[(long)(m0 + m) * K + k0 + kq * 4];
        }
    };
    auto loadX = [&](int k0) {
#pragma unroll
        for (int q = 0; q < 2; q++) {
            int e = tid + q * 256;
            int k = e >> 5, n4 = e & 31;
            xreg[q] = *(const float4*)&X[bX + (long)(k0 + k) * N + n0 + n4 * 4];
        }
    };
    auto stW = [&]() {
#pragma unroll
        for (int q = 0; q < WLD; q++) {
            int e = tid + q * 256;
            int m = e >> 2, kq = e & 3;
            float v[4] = {wreg[q].x, wreg[q].y, wreg[q].z, wreg[q].w};
#pragma unroll
            for (int j = 0; j < 4; j++) {
                u64 bits = (u64)__float_as_uint(v[j]);
                WsD[kq * 4 + j][m] = bits | (bits << 32);
            }
        }
    };
    auto stX = [&]() {
#pragma unroll
        for (int q = 0; q < 2; q++) {
            int e = tid + q * 256;
            int k = e >> 5, n4 = e & 31;
            *(float4*)&Xs[k][n4 * 4] = xreg[q];
        }
    };

    loadW(0); loadX(0);
    stW(); stX();
    __syncthreads();

    for (int k0 = 0; k0 < K; k0 += 16) {
        bool more = (k0 + 16) < K;
        if (more) { loadW(k0 + 16); loadX(k0 + 16); }
#pragma unroll
        for (int k = 0; k < 16; k++) {
            ulonglong2 wp[MT / 2];
#pragma unroll
            for (int i = 0; i < MT / 2; i++)
                wp[i] = *(const ulonglong2*)&WsD[k][ty * MT + 2 * i];
            const ulonglong2* xp = (const ulonglong2*)&Xs[k][tx * 8];
            ulonglong2 xv0 = xp[0], xv1 = xp[1];
            u64 xs[4] = {xv0.x, xv0.y, xv1.x, xv1.y};
#pragma unroll
            for (int i = 0; i < MT; i++) {
                u64 wv = (i & 1) ? wp[i >> 1].y : wp[i >> 1].x;
                fma2(acc[i][0], wv, xs[0]);
                fma2(acc[i][1], wv, xs[1]);
                fma2(acc[i][2], wv, xs[2]);
                fma2(acc[i][3], wv, xs[3]);
            }
        }
        __syncthreads();
        if (more) { stW(); stX(); __syncthreads(); }
    }

    // ---- epilogue ----
#pragma unroll
    for (int i = 0; i < MT; i++) {
        long m = m0 + ty * MT + i;
        long yoff = bY + m * (long)N + n0 + tx * 8;
        float4 v0, v1;
        v0.x = f2lo(acc[i][0]); v0.y = f2hi(acc[i][0]);
        v0.z = f2lo(acc[i][1]); v0.w = f2hi(acc[i][1]);
        v1.x = f2lo(acc[i][2]); v1.y = f2hi(acc[i][2]);
        v1.z = f2lo(acc[i][3]); v1.w = f2hi(acc[i][3]);
        if (EPI == 1) {
            float4 a0 = *(const float4*)&XN[yoff];
            float4 a1 = *(const float4*)&XN[yoff + 4];
            v0.x = fmaf(MPA_A, a0.x, MPA_B * v0.x);
            v0.y = fmaf(MPA_A, a0.y, MPA_B * v0.y);
            v0.z = fmaf(MPA_A, a0.z, MPA_B * v0.z);
            v0.w = fmaf(MPA_A, a0.w, MPA_B * v0.w);
            v1.x = fmaf(MPA_A, a1.x, MPA_B * v1.x);
            v1.y = fmaf(MPA_A, a1.y, MPA_B * v1.y);
            v1.z = fmaf(MPA_A, a1.z, MPA_B * v1.z);
            v1.w = fmaf(MPA_A, a1.w, MPA_B * v1.w);
        }
        *(float4*)&Y[yoff]     = v0;
        *(float4*)&Y[yoff + 4] = v1;
    }
}

// ---------------------------------------------------------------------------
// Depthwise 5x3 conv2d + mp_silu
// ---------------------------------------------------------------------------
__global__ void dwconv2d_kernel(const float* __restrict__ in, const float* __restrict__ wd,
                                float* __restrict__ out, int C, int F, int L) {
    int l  = blockIdx.x * blockDim.x + threadIdx.x;
    int f  = blockIdx.y;
    int zc = blockIdx.z;
    int c  = zc % C;
    const float* ip = in + (long)zc * F * L;
    const float* w  = wd + c * 15;
    float acc = 0.f;
#pragma unroll
    for (int kf = 0; kf < 5; kf++) {
        int ff = f + kf - 2;
        if (ff < 0 || ff >= F) continue;
        const float* row = ip + (long)ff * L;
#pragma unroll
        for (int kl = 0; kl < 3; kl++) {
            int ll = l + kl - 1;
            if (ll < 0 || ll >= L) continue;
            acc = fmaf(w[kf * 3 + kl], row[ll], acc);
        }
    }
    out[(long)zc * F * L + (long)f * L + l] = siluG(acc);
}

// ---------------------------------------------------------------------------
// Avg-pool over freq groups
// ---------------------------------------------------------------------------
__global__ void pool_kernel(const float* __restrict__ in, float* __restrict__ out,
                            int F, int L, int s, long total) {
    long idx = (long)blockIdx.x * blockDim.x + threadIdx.x;
    if (idx >= total) return;
    int Fo = F / s;
    long l  = idx % L;
    long fo = (idx / L) % Fo;
    long bc = idx / ((long)L * Fo);
    const float* ip = in + bc * (long)F * L + fo * s * (long)L + l;
    float acc = 0.f;
    for (int j = 0; j < s; j++) acc += ip[(long)j * L];
    out[idx] = acc * (1.0f / s);
}

// ---------------------------------------------------------------------------
// Depthwise 1D conv k=3 pad 1 on h-half of 2048-ch input, silu in & out
// ---------------------------------------------------------------------------
__global__ void dwconv1d_kernel(const float* __restrict__ in, const float* __restrict__ w,
                                float* __restrict__ out, int T, long total) {
    long idx = (long)blockIdx.x * blockDim.x + threadIdx.x;
    if (idx >= total) return;
    int  t = (int)(idx % T);
    int  c = (int)((idx / T) % 1024);
    long b = idx / ((long)1024 * T);
    const float* ip = in + ((b * 2048) + c) * (long)T;
    const float* wc = w + c * 3;
    float acc = 0.f;
    if (t > 0)     acc = fmaf(wc[0], siluG(ip[t - 1]), acc);
    acc = fmaf(wc[1], siluG(ip[t]), acc);
    if (t < T - 1) acc = fmaf(wc[2], siluG(ip[t + 1]), acc);
    out[idx] = siluG(acc);
}

// ---------------------------------------------------------------------------
// Fused minGRU: sigmoid/ab + chunked warp scan + gate, one warp per row.
// zc: (B,2048,T) [z ch0..1023 | c ch1024..2047]; hg: g at channel 1024+c;
// out: (B,1024,T) = h_scan * mp_silu(g)
// ---------------------------------------------------------------------------
__global__ void scan_fused_kernel(const float* __restrict__ zc, const float* __restrict__ hg,
                                  float* __restrict__ out, int T) {
    int row  = blockIdx.x * (blockDim.x >> 5) + (threadIdx.x >> 5);
    int lane = threadIdx.x & 31;
    int b = row >> 10, c = row & 1023;
    const float* zp = zc + ((long)(b * 2048 + c)) * T;
    const float* cp = zp + (long)1024 * T;
    const float* gp = hg + ((long)(b * 2048 + 1024 + c)) * T;
    float* op = out + ((long)(b * 1024 + c)) * T;
    int chunk = T >> 5;           // 64
    int t0 = lane * chunk;

    // pass 1: per-lane aggregate (A, B)
    float A = 1.f, Bv = 0.f;
    for (int t = t0; t < t0 + chunk; t += 4) {
        float4 z4 = *(const float4*)&zp[t];
        float4 c4 = *(const float4*)&cp[t];
        float zz[4] = {z4.x, z4.y, z4.z, z4.w};
        float cc[4] = {c4.x, c4.y, c4.z, c4.w};
#pragma unroll
        for (int j = 0; j < 4; j++) {
            float s = 1.f / (1.f + __expf(-zz[j]));
            float a = 1.f - s, bb = s * cc[j];
            Bv = fmaf(a, Bv, bb);
            A *= a;
        }
    }
    // warp inclusive scan (compose: later ∘ earlier)
    float Ai = A, Bi = Bv;
    for (int d = 1; d < 32; d <<= 1) {
        float Ar = __shfl_up_sync(0xffffffffu, Ai, d);
        float Br = __shfl_up_sync(0xffffffffu, Bi, d);
        if (lane >= d) { Bi = fmaf(Ai, Br, Bi); Ai = Ai * Ar; }
    }
    float hin = __shfl_up_sync(0xffffffffu, Bi, 1);
    if (lane == 0) hin = 0.f;

    // pass 2: recompute, apply carry, gate, store
    float h = hin;
    for (int t = t0; t < t0 + chunk; t += 4) {
        float4 z4 = *(const float4*)&zp[t];
        float4 c4 = *(const float4*)&cp[t];
        float4 g4 = *(const float4*)&gp[t];
        float zz[4] = {z4.x, z4.y, z4.z, z4.w};
        float cc[4] = {c4.x, c4.y, c4.z, c4.w};
        float gg[4] = {g4.x, g4.y, g4.z, g4.w};
        float4 o4;
        float* oo = &o4.x;
#pragma unroll
        for (int j = 0; j < 4; j++) {
            float s = 1.f / (1.f + __expf(-zz[j]));
            h = fmaf(1.f - s, h, s * cc[j]);
            oo[j] = h * siluG(gg[j]);
        }
        *(float4*)&op[t] = o4;
    }
}

// ---------------------------------------------------------------------------
// Final mp_silu
// ---------------------------------------------------------------------------
__global__ void msilu_kernel(const float* __restrict__ in, float* __restrict__ out, long n) {
    long idx = (long)blockIdx.x * blockDim.x + threadIdx.x;
    if (idx < n) out[idx] = siluG(in[idx]);
}

// ---------------------------------------------------------------------------
// Host orchestration
// ---------------------------------------------------------------------------
static inline dim3 gs(long total, int bs) { return dim3((unsigned)((total + bs - 1) / bs)); }

extern "C" void kernel_launch(void* const* d_in, const int* in_sizes, int n_in,
                              void* d_out, int out_size) {
    const float* audio = (const float*)d_in[0];
    const float* projw = (const float*)d_in[1];
    const float* projb = (const float*)d_in[2];
    const float* bw[3][4];
    for (int i = 0; i < 3; i++)
        for (int j = 0; j < 4; j++)
            bw[i][j] = (const float*)d_in[3 + i * 4 + j];
    const float* hgw_all  = (const float*)d_in[15];
    const float* dww_all  = (const float*)d_in[16];
    const float* gruw_all = (const float*)d_in[17];
    const float* outw_all = (const float*)d_in[18];

    float *xn, *y, *r1, *rd, *act, *wn;
    cudaGetSymbolAddress((void**)&xn,  g_xn);
    cudaGetSymbolAddress((void**)&y,   g_y);
    cudaGetSymbolAddress((void**)&r1,  g_r1);
    cudaGetSymbolAddress((void**)&rd,  g_rd);
    cudaGetSymbolAddress((void**)&act, g_act);
    cudaGetSymbolAddress((void**)&wn,  g_wn);

    const int B = 2, L = 2048;

    // --- projection ---
    {
        long total = (long)B * 64 * 128 * L;
        proj_kernel<<<gs(total, 256), 256>>>(audio, projw, projb, act, 128 * L, total);
    }

    // --- conv blocks ---
    int C = 64, F = 128;
    const int scales[3] = {4, 4, 8};
    for (int blk = 0; blk < 3; blk++) {
        int C2 = 2 * C;
        int S  = F * L;
        normw_kernel<<<C2, 256>>>(bw[blk][0], wn + WA, C);
        normw_kernel<<<C2, 256>>>(bw[blk][1], wn + WD, 15);
        normw_kernel<<<C , 256>>>(bw[blk][2], wn + WB, C2);
        normw_kernel<<<C2, 256>>>(bw[blk][3], wn + WC, C);

        long totP = (long)B * S;
        pn_kernel<<<gs(totP, 256), 256>>>(act, xn, y, C, S, totP);

        // r = conv(w1, silu(pn))
        gemm2_kernel<0, 128><<<dim3(S / 128, C2 / 128, B), 256>>>(wn + WA, y, r1, nullptr, C2, C, S);
        // depthwise + silu
        dwconv2d_kernel<<<dim3(L / 128, F, B * C2), 128>>>(r1, wn + WD, rd, C2, F, L);
        // h = mp_add(xn, conv(w2, rd))
        if (C == 64)
            gemm2_kernel<1, 64><<<dim3(S / 128, 1, B), 256>>>(wn + WB, rd, y, xn, C, C2, S);
        else
            gemm2_kernel<1, 128><<<dim3(S / 128, C / 128, B), 256>>>(wn + WB, rd, y, xn, C, C2, S);

        int s = scales[blk], Fo = F / s;
        long totPool = (long)B * C * Fo * L;
        pool_kernel<<<gs(totPool, 256), 256>>>(y, r1, F, L, s, totPool);

        int S2 = Fo * L;
        gemm2_kernel<0, 128><<<dim3(S2 / 128, C2 / 128, B), 256>>>(wn + WC, r1, act, nullptr, C2, C, S2);
        C = C2; F = Fo;
    }

    // --- sequence blocks (act: (B, 512, 2048)) ---
    const int T = 2048;
    for (int i = 0; i < 4; i++) {
        const float* hgw  = hgw_all  + (long)i * 2048 * 512;
        const float* dww  = dww_all  + (long)i * 1024 * 3;
        const float* gruw = gruw_all + (long)i * 2048 * 1024;
        const float* outw = outw_all + (long)i * 512 * 1024;
        normw_kernel<<<2048, 256>>>(hgw,  wn + WB, 512);
        normw_kernel<<<1024, 256>>>(dww,  wn + WD, 3);
        normw_kernel<<<2048, 256>>>(gruw, wn + WA, 1024);
        normw_kernel<<< 512, 256>>>(outw, wn + WC, 1024);

        pn_seq_kernel<<<(B * T) / 32, 256>>>(act, xn, 512, T);

        // hg = conv(hg_w, xn)  -> r1 (B,2048,T)
        gemm2_kernel<0, 128><<<dim3(T / 128, 2048 / 128, B), 256>>>(wn + WB, xn, r1, nullptr, 2048, 512, T);

        // depthwise 1d on silu(h half) -> rd (B,1024,T)
        long tot1 = (long)B * 1024 * T;
        dwconv1d_kernel<<<gs(tot1, 256), 256>>>(r1, wn + WD, rd, T, tot1);

        // zc = conv(gru_w, rd) -> y (B,2048,T)
        gemm2_kernel<0, 128><<<dim3(T / 128, 2048 / 128, B), 256>>>(wn + WA, rd, y, nullptr, 2048, 1024, T);

        // fused sigmoid + scan + gate -> rd (B,1024,T)
        scan_fused_kernel<<<(B * 1024) / 8, 256>>>(y, r1, rd, T);

        // act = mp_add(xn, conv(out_w, rd))
        gemm2_kernel<1, 128><<<dim3(T / 128, 512 / 128, B), 256>>>(wn + WC, rd, act, xn, 512, 1024, T);
    }

    // --- final mp_silu ---
    msilu_kernel<<<gs(out_size, 256), 256>>>(act, (float*)d_out, (long)out_size);
}